// round 1
// baseline (speedup 1.0000x reference)
#include <cuda_runtime.h>
#include <math_constants.h>

// Problem constants (fixed shapes for this dataset)
#define NMAX 50000
#define EMAX 1600000
#define HD 64   // H*D
#define NH 8    // heads

// ---- scratch (static device globals; no allocation allowed) ----
__device__ float g_h[NMAX * HD];       // per-layer projected features
__device__ float g_esrc[NMAX * NH];    // per-node src attention logits
__device__ float g_edst[NMAX * NH];    // per-node dst attention logits
__device__ float g_xbuf[NMAX * HD];    // inter-layer activations
__device__ int   g_rowoff[NMAX + 1];   // CSR row offsets (by dst)
__device__ int   g_cursor[NMAX];       // degree counts / fill cursors
__device__ int   g_csrc[EMAX];         // CSR: src node per incoming edge

// ---------------- CSR construction ----------------
__global__ void zero_counts(int n) {
    int i = blockIdx.x * blockDim.x + threadIdx.x;
    if (i < n) g_cursor[i] = 0;
}

__global__ void count_deg(const int* __restrict__ dst, int e) {
    int i = blockIdx.x * blockDim.x + threadIdx.x;
    if (i < e) atomicAdd(&g_cursor[dst[i]], 1);
}

// single-block exclusive scan over n counts -> row offsets + fill cursors
__global__ void scan_kernel(int n) {
    __shared__ int sums[1024];
    int tid = threadIdx.x;
    int ch = (n + 1023) / 1024;
    int start = tid * ch;
    int local = 0;
    for (int i = 0; i < ch; i++) {
        int idx = start + i;
        if (idx < n) local += g_cursor[idx];
    }
    sums[tid] = local;
    __syncthreads();
    for (int off = 1; off < 1024; off <<= 1) {
        int v = (tid >= off) ? sums[tid - off] : 0;
        __syncthreads();
        sums[tid] += v;
        __syncthreads();
    }
    int run = sums[tid] - local;  // exclusive prefix
    for (int i = 0; i < ch; i++) {
        int idx = start + i;
        if (idx < n) {
            int c = g_cursor[idx];
            g_rowoff[idx] = run;
            g_cursor[idx] = run;   // fill cursor
            run += c;
        }
    }
    if (tid == 1023) g_rowoff[n] = sums[1023];
}

__global__ void fill_csr(const int* __restrict__ src, const int* __restrict__ dst, int e) {
    int i = blockIdx.x * blockDim.x + threadIdx.x;
    if (i < e) {
        int pos = atomicAdd(&g_cursor[dst[i]], 1);
        g_csrc[pos] = src[i];
    }
}

// ---------------- fused GEMM + attention logits ----------------
// One warp per node row. Thread `lane` owns output cols (2*lane, 2*lane+1).
// Computes h = x @ W, e_src = <h, att[0]>, e_dst = <h, att[1]> per head.
template <int FIN>
__global__ void gemm_att(const float* __restrict__ xin,
                         const float* __restrict__ W,
                         const float* __restrict__ att, int n) {
    __shared__ float2 sW[FIN * 32];
    __shared__ float  sx[8][FIN];
    int tid = threadIdx.x;
    const float2* W2 = (const float2*)W;
    for (int i = tid; i < FIN * 32; i += 256) sW[i] = W2[i];

    int warp = tid >> 5, lane = tid & 31;
    int row = blockIdx.x * 8 + warp;
    const float* xp = xin ? xin : g_xbuf;
    if (row < n)
        for (int k = lane; k < FIN; k += 32) sx[warp][k] = xp[row * FIN + k];
    __syncthreads();
    if (row >= n) return;

    float a0 = 0.f, a1 = 0.f;
#pragma unroll
    for (int k = 0; k < FIN; k++) {
        float xv = sx[warp][k];
        float2 w = sW[k * 32 + lane];
        a0 = fmaf(xv, w.x, a0);
        a1 = fmaf(xv, w.y, a1);
    }
    ((float2*)g_h)[row * 32 + lane] = make_float2(a0, a1);

    int head = lane >> 2;
    int d = (2 * lane) & 7;
    float p0 = a0 * att[head * 8 + d]      + a1 * att[head * 8 + d + 1];
    float p1 = a0 * att[64 + head * 8 + d] + a1 * att[64 + head * 8 + d + 1];
    p0 += __shfl_xor_sync(0xffffffffu, p0, 1);
    p0 += __shfl_xor_sync(0xffffffffu, p0, 2);
    p1 += __shfl_xor_sync(0xffffffffu, p1, 1);
    p1 += __shfl_xor_sync(0xffffffffu, p1, 2);
    if ((lane & 3) == 0) {
        g_esrc[row * NH + head] = p0;
        g_edst[row * NH + head] = p1;
    }
}

// ---------------- per-dst online-softmax aggregation ----------------
// One warp per dst node; single pass over incoming edges (flash-style).
__global__ void agg_kernel(const float* __restrict__ bias,
                           float* __restrict__ xout, int apply_elu, int n) {
    int wg = (blockIdx.x * blockDim.x + threadIdx.x) >> 5;
    int lane = threadIdx.x & 31;
    if (wg >= n) return;
    int head = lane >> 2;
    float ed = g_edst[wg * NH + head];
    int beg = g_rowoff[wg], end = g_rowoff[wg + 1];
    const float2* h2 = (const float2*)g_h;

    float m = -CUDART_INF_F, s = 0.f, ax = 0.f, ay = 0.f;
    for (int i = beg; i < end; i++) {
        int srcn = g_csrc[i];
        float es = g_esrc[srcn * NH + head];
        float v = es + ed;
        float e = v > 0.f ? v : 0.2f * v;        // leaky relu
        float2 hv = h2[srcn * 32 + lane];
        float nm = fmaxf(m, e);
        float c = __expf(m - nm);                // exp(-inf)=0 handles first edge
        float p = __expf(e - nm);
        s  = s  * c + p;
        ax = ax * c + p * hv.x;
        ay = ay * c + p * hv.y;
        m = nm;
    }
    float inv = 1.f / (s + 1e-16f);
    float o0 = ax * inv + bias[2 * lane];
    float o1 = ay * inv + bias[2 * lane + 1];
    if (apply_elu) {
        o0 = o0 > 0.f ? o0 : expm1f(o0);
        o1 = o1 > 0.f ? o1 : expm1f(o1);
    }
    float* dest = xout ? xout : g_xbuf;
    ((float2*)dest)[wg * 32 + lane] = make_float2(o0, o1);
}

// ---------------- launch ----------------
extern "C" void kernel_launch(void* const* d_in, const int* in_sizes, int n_in,
                              void* d_out, int out_size) {
    const float* x  = (const float*)d_in[0];
    const int*   ei = (const int*)d_in[1];
    int n = in_sizes[0] / 128;
    int e = in_sizes[1] / 2;
    const int* src = ei;
    const int* dst = ei + e;

    const float* W[4], *att[4], *b[4];
    for (int l = 0; l < 4; l++) {
        W[l]   = (const float*)d_in[2 + 3 * l];
        att[l] = (const float*)d_in[3 + 3 * l];
        b[l]   = (const float*)d_in[4 + 3 * l];
    }

    // CSR build (per call; deterministic up to within-node order)
    zero_counts<<<(n + 255) / 256, 256>>>(n);
    count_deg<<<(e + 255) / 256, 256>>>(dst, e);
    scan_kernel<<<1, 1024>>>(n);
    fill_csr<<<(e + 255) / 256, 256>>>(src, dst, e);

    int gblk = (n + 7) / 8;  // 8 warps/block, warp-per-node

    // layer 0 (FIN=128)
    gemm_att<128><<<gblk, 256>>>(x, W[0], att[0], n);
    agg_kernel<<<gblk, 256>>>(b[0], nullptr, 1, n);
    // layers 1,2 (FIN=64, ELU)
    gemm_att<64><<<gblk, 256>>>(nullptr, W[1], att[1], n);
    agg_kernel<<<gblk, 256>>>(b[1], nullptr, 1, n);
    gemm_att<64><<<gblk, 256>>>(nullptr, W[2], att[2], n);
    agg_kernel<<<gblk, 256>>>(b[2], nullptr, 1, n);
    // layer 3 (no ELU, write to d_out)
    gemm_att<64><<<gblk, 256>>>(nullptr, W[3], att[3], n);
    agg_kernel<<<gblk, 256>>>(b[3], (float*)d_out, 0, n);
}